// round 3
// baseline (speedup 1.0000x reference)
#include <cuda_runtime.h>
#include <cstdint>

#define BATCH 256
#define NN 256
#define MM 256
#define DIM 32
#define BIGF 1e8f
#define XP 132                 // xsT pitch (floats)
#define YP 68                  // ysT pitch (floats)
#define RING_FLOATS (4 * 4096) // 4 slots x 16 tiles x 256 floats = 64KB
#define BUF_STRIDE 264
#define SMEM_DP ((RING_FLOATS + 3 * BUF_STRIDE) * 4)

// dist in 16x16-tiled layout: [b][tile = (r>>4)*16 + (c>>4)][ (r&15)*16 + (c&15) ]
__device__ float g_dist[BATCH * NN * MM];
__device__ float g_partial[BATCH];

typedef unsigned long long u64;

__device__ __forceinline__ u64 pack2f(float a, float b) {
    u64 r;
    asm("mov.b64 %0, {%1, %2};" : "=l"(r) : "f"(a), "f"(b));
    return r;
}
__device__ __forceinline__ u64 fma2f(u64 a, u64 b, u64 c) {
    u64 d;
    asm("fma.rn.f32x2 %0, %1, %2, %3;" : "=l"(d) : "l"(a), "l"(b), "l"(c));
    return d;
}
__device__ __forceinline__ float lo32(u64 v) {
    return __uint_as_float((unsigned)(v & 0xffffffffull));
}
__device__ __forceinline__ float hi32(u64 v) {
    return __uint_as_float((unsigned)(v >> 32));
}

// ---------------------------------------------------------------------------
// Kernel 1: tiled GEMM distance. Grid = BATCH * 8 (2 i-tiles x 4 j-tiles of
// a 128x64 block tile). 256 threads as 16x16; each thread computes an 8x4
// register tile with packed f32x2 FMAs (i-pairs packed). Output written as
// 16x16 tiles (coalesced float4 stores).
// ---------------------------------------------------------------------------
__global__ __launch_bounds__(256) void dist_kernel(const float* __restrict__ x,
                                                   const float* __restrict__ y) {
    __shared__ float xsT[DIM * XP];
    __shared__ float ysT[DIM * YP];
    __shared__ float x2s[128];
    __shared__ float y2s[64];

    const int bx = blockIdx.x;
    const int b = bx >> 3, sub = bx & 7;
    const int ibase = (sub >> 2) * 128, jbase = (sub & 3) * 64;
    const int t = threadIdx.x;

    const float* xb = x + ((size_t)b * NN + ibase) * DIM;
    const float* yb = y + ((size_t)b * MM + jbase) * DIM;

    for (int e = t; e < 128 * DIM; e += 256) xsT[(e & 31) * XP + (e >> 5)] = xb[e];
    for (int e = t; e < 64 * DIM; e += 256) ysT[(e & 31) * YP + (e >> 5)] = yb[e];
    __syncthreads();

    if (t < 128) {
        float s = 0.f;
#pragma unroll 8
        for (int k = 0; k < DIM; k++) { float v = xsT[k * XP + t]; s = fmaf(v, v, s); }
        x2s[t] = s;
    } else if (t < 192) {
        int j = t - 128;
        float s = 0.f;
#pragma unroll 8
        for (int k = 0; k < DIM; k++) { float v = ysT[k * YP + j]; s = fmaf(v, v, s); }
        y2s[j] = s;
    }
    __syncthreads();

    const int ti = t >> 4, tj = t & 15;
    const int i0 = ti * 8, j0 = tj * 4;

    u64 acc[4][4];
#pragma unroll
    for (int a = 0; a < 4; a++)
#pragma unroll
        for (int q = 0; q < 4; q++) acc[a][q] = 0ull;

#pragma unroll 8
    for (int k = 0; k < DIM; k++) {
        ulonglong2 xv = *(const ulonglong2*)(xsT + k * XP + i0);
        ulonglong2 xw = *(const ulonglong2*)(xsT + k * XP + i0 + 4);
        float4 yv = *(const float4*)(ysT + k * YP + j0);
        u64 yp0 = pack2f(yv.x, yv.x), yp1 = pack2f(yv.y, yv.y);
        u64 yp2 = pack2f(yv.z, yv.z), yp3 = pack2f(yv.w, yv.w);
        acc[0][0] = fma2f(xv.x, yp0, acc[0][0]);
        acc[0][1] = fma2f(xv.x, yp1, acc[0][1]);
        acc[0][2] = fma2f(xv.x, yp2, acc[0][2]);
        acc[0][3] = fma2f(xv.x, yp3, acc[0][3]);
        acc[1][0] = fma2f(xv.y, yp0, acc[1][0]);
        acc[1][1] = fma2f(xv.y, yp1, acc[1][1]);
        acc[1][2] = fma2f(xv.y, yp2, acc[1][2]);
        acc[1][3] = fma2f(xv.y, yp3, acc[1][3]);
        acc[2][0] = fma2f(xw.x, yp0, acc[2][0]);
        acc[2][1] = fma2f(xw.x, yp1, acc[2][1]);
        acc[2][2] = fma2f(xw.x, yp2, acc[2][2]);
        acc[2][3] = fma2f(xw.x, yp3, acc[2][3]);
        acc[3][0] = fma2f(xw.y, yp0, acc[3][0]);
        acc[3][1] = fma2f(xw.y, yp1, acc[3][1]);
        acc[3][2] = fma2f(xw.y, yp2, acc[3][2]);
        acc[3][3] = fma2f(xw.y, yp3, acc[3][3]);
    }

    float* gb = g_dist + (size_t)b * (NN * MM);
    const int c0 = jbase + j0;
    const int ctile = c0 >> 4, cin = c0 & 15;
    float w0 = y2s[j0], w1 = y2s[j0 + 1], w2 = y2s[j0 + 2], w3 = y2s[j0 + 3];

#pragma unroll
    for (int ip = 0; ip < 4; ip++) {
        int rlA = i0 + 2 * ip, rlB = rlA + 1;
        int rA = ibase + rlA, rB = rA + 1;
        float xA = x2s[rlA], xB = x2s[rlB];
        float4 vA, vB;
        vA.x = fmaxf(fmaf(-2.f, lo32(acc[ip][0]), xA + w0), 0.f);
        vA.y = fmaxf(fmaf(-2.f, lo32(acc[ip][1]), xA + w1), 0.f);
        vA.z = fmaxf(fmaf(-2.f, lo32(acc[ip][2]), xA + w2), 0.f);
        vA.w = fmaxf(fmaf(-2.f, lo32(acc[ip][3]), xA + w3), 0.f);
        vB.x = fmaxf(fmaf(-2.f, hi32(acc[ip][0]), xB + w0), 0.f);
        vB.y = fmaxf(fmaf(-2.f, hi32(acc[ip][1]), xB + w1), 0.f);
        vB.z = fmaxf(fmaf(-2.f, hi32(acc[ip][2]), xB + w2), 0.f);
        vB.w = fmaxf(fmaf(-2.f, hi32(acc[ip][3]), xB + w3), 0.f);
        *(float4*)(gb + ((rA >> 4) * 16 + ctile) * 256 + ((rA & 15) << 4) + cin) = vA;
        *(float4*)(gb + ((rB >> 4) * 16 + ctile) * 256 + ((rB & 15) << 4) + cin) = vB;
    }
}

// ---------------------------------------------------------------------------
// Kernel 2: anti-diagonal wavefront DP. One block per batch, thread t owns
// column j=t+1. dist streams through a 4-slot ring of 16-diagonal sub-bands
// (16 tiles of 16x16 = 16KB per band) via cp.async. Softmin uses the exact
// median trick: s = 1 + exp(mn-mid) + exp(mn-mx)  (3 MUFU instead of 4).
// ---------------------------------------------------------------------------
__device__ __forceinline__ void issue_band(int T, const float* gb, uint32_t ringS, int t) {
    if (T > 30) return;
    int rt0 = T - 15 > 0 ? T - 15 : 0;
    int rt1 = T < 15 ? T : 15;
    int chunks = (rt1 - rt0 + 1) * 64;   // 16B chunks in this band
    uint32_t slotbase = ringS + (uint32_t)((T & 3) * 4096 * 4);
    for (int n = t; n < chunks; n += 256) {
        int tile = n >> 6, wi = n & 63;
        int rt = rt0 + tile;
        const float* g = gb + ((rt * 16 + (T - rt)) * 256 + wi * 4);
        uint32_t s = slotbase + (uint32_t)(((rt & 15) * 256 + wi * 4) * 4);
        asm volatile("cp.async.cg.shared.global [%0], [%1], 16;" :: "r"(s), "l"(g));
    }
}

__global__ __launch_bounds__(256) void dtw_kernel() {
    extern __shared__ float sm[];
    float* ring = sm;
    float* buf  = sm + RING_FLOATS;
    const int b = blockIdx.x, t = threadIdx.x, j = t + 1;

    float* bA = buf;                  // diag p-2
    float* bB = buf + BUF_STRIDE;     // diag p-1
    float* bC = buf + 2 * BUF_STRIDE;

    for (int idx = t; idx < 3 * BUF_STRIDE; idx += 256) buf[idx] = BIGF;
    if (t == 0) bA[0] = 0.f;   // D[0][0]

    const float* gb = g_dist + (size_t)b * (NN * MM);
    uint32_t ringS = (uint32_t)__cvta_generic_to_shared(ring);

    issue_band(0, gb, ringS, t);
    asm volatile("cp.async.commit_group;");

    float* cur2 = bA; float* cur1 = bB; float* cur0 = bC;
    float myprev = BIGF;

    for (int p = 2; p <= NN + MM; ++p) {
        int q = p - 2;
        if ((q & 15) == 0) {
            int U = q >> 4;
            issue_band(U + 1, gb, ringS, t);
            asm volatile("cp.async.commit_group;");
            asm volatile("cp.async.wait_group 1;");
            __syncthreads();   // band U visible; also covers buffer init at p=2
        }

        int i = p - j;
        float nv = BIGF;
        if (i >= 1 && i <= NN) {
            int r = i - 1, c = t;
            int rt = r >> 4, ct = c >> 4;
            float dq = ring[((rt + ct) & 3) * 4096 + (rt & 15) * 256 +
                            ((r & 15) << 4) + (c & 15)];
            float lf = cur1[t];                  // D[i][j-1]
            float dg = cur2[t];                  // D[i-1][j-1]
            float up = myprev;                   // D[i-1][j]
            float mn = fminf(fminf(up, lf), dg);
            float mx = fmaxf(fmaxf(up, lf), dg);
            float md = fmaxf(fminf(up, lf), fminf(fmaxf(up, lf), dg));  // exact median
            float s  = 1.0f + __expf(mn - md) + __expf(mn - mx);
            nv = dq + mn - __logf(s);
            cur0[j] = nv;
        }
        if (j == p) cur0[j] = BIGF;   // top border D[0][p]
        if (t == 0) cur0[0] = BIGF;   // left border D[p][0]
        myprev = nv;
        if (p == NN + MM && t == 255) g_partial[b] = nv;
        __syncthreads();
        float* tmp = cur2; cur2 = cur1; cur1 = cur0; cur0 = tmp;
    }
}

// ---------------------------------------------------------------------------
// Kernel 3: mean over batches -> scalar output.
// ---------------------------------------------------------------------------
__global__ __launch_bounds__(256) void reduce_kernel(float* __restrict__ out) {
    __shared__ float sb[256];
    int t = threadIdx.x;
    sb[t] = g_partial[t];
    __syncthreads();
    for (int s = 128; s > 0; s >>= 1) {
        if (t < s) sb[t] += sb[t + s];
        __syncthreads();
    }
    if (t == 0) out[0] = sb[0] * (1.0f / BATCH);
}

extern "C" void kernel_launch(void* const* d_in, const int* in_sizes, int n_in,
                              void* d_out, int out_size) {
    (void)in_sizes; (void)n_in; (void)out_size;
    const float* x = (const float*)d_in[0];
    const float* y = (const float*)d_in[1];
    float* out = (float*)d_out;

    cudaFuncSetAttribute(dtw_kernel, cudaFuncAttributeMaxDynamicSharedMemorySize, SMEM_DP);

    dist_kernel<<<BATCH * 8, 256>>>(x, y);
    dtw_kernel<<<BATCH, 256, SMEM_DP>>>();
    reduce_kernel<<<1, 256>>>(out);
}

// round 5
// speedup vs baseline: 1.8990x; 1.8990x over previous
#include <cuda_runtime.h>
#include <cuda_bf16.h>
#include <cstdint>

#define BATCH 256
#define NN 256
#define MM 256
#define DIM 32
#define BIGF 1e8f

// dist in 16x16-tiled layout: [b][tile=(r>>4)*16+(c>>4)][(r&15)*16+(c&15)]
__device__ float g_dist[BATCH * NN * MM];
__device__ float g_partial[BATCH];

__device__ __forceinline__ uint32_t smem_u32(const void* p) {
    uint32_t a;
    asm("{ .reg .u64 t; cvta.to.shared.u64 t, %1; cvt.u32.u64 %0, t; }" : "=r"(a) : "l"(p));
    return a;
}
__device__ __forceinline__ void ldmx4(uint32_t* r, uint32_t addr) {
    asm volatile("ldmatrix.sync.aligned.m8n8.x4.shared.b16 {%0,%1,%2,%3}, [%4];"
                 : "=r"(r[0]), "=r"(r[1]), "=r"(r[2]), "=r"(r[3]) : "r"(addr));
}
__device__ __forceinline__ void mma16816(float* c, const uint32_t* a, uint32_t b0,
                                         uint32_t b1) {
    asm volatile(
        "mma.sync.aligned.m16n8k16.row.col.f32.bf16.bf16.f32 "
        "{%0,%1,%2,%3}, {%4,%5,%6,%7}, {%8,%9}, {%0,%1,%2,%3};"
        : "+f"(c[0]), "+f"(c[1]), "+f"(c[2]), "+f"(c[3])
        : "r"(a[0]), "r"(a[1]), "r"(a[2]), "r"(a[3]), "r"(b0), "r"(b1));
}

#define PITCHB 80   // bytes per bf16 row (40 bf16); 8-row ldmatrix conflict-free

// ---------------------------------------------------------------------------
// Kernel 1: dist via mma.sync bf16. One CTA per batch; 8 warps, each a
// 32-row stripe x 256 cols. TN GEMM: A = x rows, B = y rows, k fast, no
// .trans ldmatrix. Epilogue: D = x2 + y2 - 2*dot (norms exact fp32), clamp,
// store 16x16-tiled as float2 pairs.
// ---------------------------------------------------------------------------
__global__ __launch_bounds__(256) void dist_kernel(const float* __restrict__ x,
                                                   const float* __restrict__ y) {
    __shared__ __align__(16) char xs[256 * PITCHB];
    __shared__ __align__(16) char ys[256 * PITCHB];
    __shared__ float x2s[256];
    __shared__ float y2s[256];

    const int b = blockIdx.x, t = threadIdx.x;
    const int w = t >> 5, lane = t & 31;
    const float* xr = x + ((size_t)b * NN + t) * DIM;
    const float* yr = y + ((size_t)b * MM + t) * DIM;

    // convert row t of x and y to bf16 smem; exact fp32 norms
    {
        float sx = 0.f, sy = 0.f;
#pragma unroll
        for (int q = 0; q < 8; q++) {
            float4 v = *(const float4*)(xr + q * 4);
            sx = fmaf(v.x, v.x, fmaf(v.y, v.y, fmaf(v.z, v.z, fmaf(v.w, v.w, sx))));
            uint2 wv;
            asm("cvt.rn.bf16x2.f32 %0, %1, %2;" : "=r"(wv.x) : "f"(v.y), "f"(v.x));
            asm("cvt.rn.bf16x2.f32 %0, %1, %2;" : "=r"(wv.y) : "f"(v.w), "f"(v.z));
            *(uint2*)(xs + t * PITCHB + q * 8) = wv;
            float4 u = *(const float4*)(yr + q * 4);
            sy = fmaf(u.x, u.x, fmaf(u.y, u.y, fmaf(u.z, u.z, fmaf(u.w, u.w, sy))));
            uint2 uv;
            asm("cvt.rn.bf16x2.f32 %0, %1, %2;" : "=r"(uv.x) : "f"(u.y), "f"(u.x));
            asm("cvt.rn.bf16x2.f32 %0, %1, %2;" : "=r"(uv.y) : "f"(u.w), "f"(u.z));
            *(uint2*)(ys + t * PITCHB + q * 8) = uv;
        }
        x2s[t] = sx;
        y2s[t] = sy;
    }
    __syncthreads();

    const uint32_t xsb = smem_u32(xs), ysb = smem_u32(ys);
    const int i0w = w * 32;

    // A fragments for both 16-row tiles and both k-steps: a[rt][ks][4]
    uint32_t afr[2][2][4];
    {
        int rowA = i0w + (lane & 15);
        uint32_t base = xsb + rowA * PITCHB + ((lane >> 4) << 4);
#pragma unroll
        for (int rt = 0; rt < 2; rt++)
#pragma unroll
            for (int ks = 0; ks < 2; ks++)
                ldmx4(afr[rt][ks], base + rt * 16 * PITCHB + ks * 32);
    }

    float* gb = g_dist + (size_t)b * (NN * MM);
    const int rsub = lane >> 2;             // 0..7
    const int cpair = 2 * (lane & 3);       // 0,2,4,6

    for (int cg = 0; cg < 16; cg++) {
        const int c0 = cg * 16;
        // B fragments: rows c0+(lane&7)+((lane&16)>>1), kbyte = ((lane>>3)&1)*16
        uint32_t bbase = ysb + (c0 + (lane & 7) + ((lane & 16) >> 1)) * PITCHB +
                         ((lane >> 3) & 1) * 16;
        uint32_t b_k0[4], b_k1[4];
        ldmx4(b_k0, bbase);        // k 0..15 : {nt0.b0, nt0.b1, nt1.b0, nt1.b1}
        ldmx4(b_k1, bbase + 32);   // k 16..31

#pragma unroll
        for (int rt = 0; rt < 2; rt++) {
            float C0[4] = {0.f, 0.f, 0.f, 0.f};
            float C1[4] = {0.f, 0.f, 0.f, 0.f};
            mma16816(C0, afr[rt][0], b_k0[0], b_k0[1]);
            mma16816(C0, afr[rt][1], b_k1[0], b_k1[1]);
            mma16816(C1, afr[rt][0], b_k0[2], b_k0[3]);
            mma16816(C1, afr[rt][1], b_k1[2], b_k1[3]);

            const int r_lo = i0w + rt * 16 + rsub;
            const float x2lo = x2s[r_lo], x2hi = x2s[r_lo + 8];
            const int rowtile = ((r_lo >> 4) * 16 + cg) * 256;
            const int rin_lo = (r_lo & 15) << 4, rin_hi = ((r_lo + 8) & 15) << 4;
#pragma unroll
            for (int nt = 0; nt < 2; nt++) {
                const float* C = nt ? C1 : C0;
                const int cc = c0 + nt * 8 + cpair;
                float2 yy = *(const float2*)(y2s + cc);
                float2 olo, ohi;
                olo.x = fmaxf(fmaf(-2.f, C[0], x2lo + yy.x), 0.f);
                olo.y = fmaxf(fmaf(-2.f, C[1], x2lo + yy.y), 0.f);
                ohi.x = fmaxf(fmaf(-2.f, C[2], x2hi + yy.x), 0.f);
                ohi.y = fmaxf(fmaf(-2.f, C[3], x2hi + yy.y), 0.f);
                const int cin = nt * 8 + cpair;
                *(float2*)(gb + rowtile + rin_lo + cin) = olo;
                *(float2*)(gb + rowtile + rin_hi + cin) = ohi;
            }
        }
    }
}

// ---------------------------------------------------------------------------
// Kernel 2: wavefront DP, 2 batches per CTA (ILP-2). 128 CTAs = 1/SM.
// Thread t owns column j=t+1 of both batches; independent softmin chains
// overlap MUFU/LDS latency. dist streams via cp.async 4-slot band rings.
// ---------------------------------------------------------------------------
#define RINGF 16384                 // floats per batch ring (4 slots x 4096)
#define BUFS 264
#define SMEM_DP ((2 * RINGF + 6 * BUFS) * 4)

__device__ __forceinline__ void issue_band(int T, const float* gb, uint32_t ringS, int t) {
    if (T > 30) return;
    int rt0 = T - 15 > 0 ? T - 15 : 0;
    int rt1 = T < 15 ? T : 15;
    int chunks = (rt1 - rt0 + 1) * 64;
    uint32_t slotbase = ringS + (uint32_t)((T & 3) * 4096 * 4);
    for (int n = t; n < chunks; n += 256) {
        int tile = n >> 6, wi = n & 63;
        int rt = rt0 + tile;
        const float* g = gb + ((rt * 16 + (T - rt)) * 256 + wi * 4);
        uint32_t s = slotbase + (uint32_t)(((rt & 15) * 256 + wi * 4) * 4);
        asm volatile("cp.async.cg.shared.global [%0], [%1], 16;" :: "r"(s), "l"(g));
    }
}

__global__ __launch_bounds__(256) void dtw_kernel() {
    extern __shared__ float sm[];
    float* ring0 = sm;
    float* ring1 = sm + RINGF;
    float* buf = sm + 2 * RINGF;
    const int bb = blockIdx.x, t = threadIdx.x, j = t + 1;
    const float* gb0 = g_dist + (size_t)(2 * bb) * (NN * MM);
    const float* gb1 = g_dist + (size_t)(2 * bb + 1) * (NN * MM);
    uint32_t rs0 = smem_u32(ring0), rs1 = smem_u32(ring1);

    float *c2_0 = buf,            *c1_0 = buf + BUFS,     *c0_0 = buf + 2 * BUFS;
    float *c2_1 = buf + 3 * BUFS, *c1_1 = buf + 4 * BUFS, *c0_1 = buf + 5 * BUFS;

    for (int idx = t; idx < 6 * BUFS; idx += 256) buf[idx] = BIGF;
    if (t == 0) { c2_0[0] = 0.f; c2_1[0] = 0.f; }

    issue_band(0, gb0, rs0, t);
    issue_band(0, gb1, rs1, t);
    asm volatile("cp.async.commit_group;");

    float mp0 = BIGF, mp1 = BIGF;

    for (int p = 2; p <= NN + MM; ++p) {
        int q = p - 2;
        if ((q & 15) == 0) {
            int U = q >> 4;
            issue_band(U + 1, gb0, rs0, t);
            issue_band(U + 1, gb1, rs1, t);
            asm volatile("cp.async.commit_group;");
            asm volatile("cp.async.wait_group 1;");
            __syncthreads();   // band U visible; also covers buffer init at p=2
        }

        int i = p - j;
        float nv0 = BIGF, nv1 = BIGF;
        if (i >= 1 && i <= NN) {
            int r = i - 1, c = t;
            int off = (((r >> 4) + (c >> 4)) & 3) * 4096 + ((r >> 4) & 15) * 256 +
                      ((r & 15) << 4) + (c & 15);
            float dq0 = ring0[off], dq1 = ring1[off];
            float lf0 = c1_0[t], dg0 = c2_0[t], up0 = mp0;
            float lf1 = c1_1[t], dg1 = c2_1[t], up1 = mp1;

            float mn0 = fminf(fminf(up0, lf0), dg0);
            float mx0 = fmaxf(fmaxf(up0, lf0), dg0);
            float md0 = fmaxf(fminf(up0, lf0), fminf(fmaxf(up0, lf0), dg0));
            float mn1 = fminf(fminf(up1, lf1), dg1);
            float mx1 = fmaxf(fmaxf(up1, lf1), dg1);
            float md1 = fmaxf(fminf(up1, lf1), fminf(fmaxf(up1, lf1), dg1));
            float s0 = 1.0f + __expf(mn0 - md0) + __expf(mn0 - mx0);
            float s1 = 1.0f + __expf(mn1 - md1) + __expf(mn1 - mx1);
            nv0 = dq0 + mn0 - __logf(s0);
            nv1 = dq1 + mn1 - __logf(s1);
            c0_0[j] = nv0;
            c0_1[j] = nv1;
        }
        if (j == p) { c0_0[j] = BIGF; c0_1[j] = BIGF; }   // top border D[0][p]
        if (t == 0) { c0_0[0] = BIGF; c0_1[0] = BIGF; }   // left border D[p][0]
        mp0 = nv0; mp1 = nv1;
        if (p == NN + MM && t == 255) {
            g_partial[2 * bb] = nv0;
            g_partial[2 * bb + 1] = nv1;
        }
        __syncthreads();
        float* tmp;
        tmp = c2_0; c2_0 = c1_0; c1_0 = c0_0; c0_0 = tmp;
        tmp = c2_1; c2_1 = c1_1; c1_1 = c0_1; c0_1 = tmp;
    }
}

// ---------------------------------------------------------------------------
// Kernel 3: mean over batches -> scalar output.
// ---------------------------------------------------------------------------
__global__ __launch_bounds__(256) void reduce_kernel(float* __restrict__ out) {
    __shared__ float sb[256];
    int t = threadIdx.x;
    sb[t] = g_partial[t];
    __syncthreads();
    for (int s = 128; s > 0; s >>= 1) {
        if (t < s) sb[t] += sb[t + s];
        __syncthreads();
    }
    if (t == 0) out[0] = sb[0] * (1.0f / BATCH);
}

extern "C" void kernel_launch(void* const* d_in, const int* in_sizes, int n_in,
                              void* d_out, int out_size) {
    (void)in_sizes; (void)n_in; (void)out_size;
    const float* x = (const float*)d_in[0];
    const float* y = (const float*)d_in[1];
    float* out = (float*)d_out;

    cudaFuncSetAttribute(dtw_kernel, cudaFuncAttributeMaxDynamicSharedMemorySize,
                         SMEM_DP);

    dist_kernel<<<BATCH, 256>>>(x, y);
    dtw_kernel<<<BATCH / 2, 256, SMEM_DP>>>();
    reduce_kernel<<<1, 256>>>(out);
}

// round 6
// speedup vs baseline: 2.0802x; 1.0954x over previous
#include <cuda_runtime.h>
#include <cuda_bf16.h>
#include <cstdint>

#define BATCH 256
#define NN 256
#define MM 256
#define DIM 32
#define BIGF 1e8f

// dist in 16x16-tiled layout: [b][tile=(r>>4)*16+(c>>4)][(r&15)*16+(c&15)]
__device__ float g_dist[BATCH * NN * MM];
__device__ float g_partial[BATCH];

__device__ __forceinline__ uint32_t smem_u32(const void* p) {
    uint32_t a;
    asm("{ .reg .u64 t; cvta.to.shared.u64 t, %1; cvt.u32.u64 %0, t; }" : "=r"(a) : "l"(p));
    return a;
}
__device__ __forceinline__ void ldmx4(uint32_t* r, uint32_t addr) {
    asm volatile("ldmatrix.sync.aligned.m8n8.x4.shared.b16 {%0,%1,%2,%3}, [%4];"
                 : "=r"(r[0]), "=r"(r[1]), "=r"(r[2]), "=r"(r[3]) : "r"(addr));
}
__device__ __forceinline__ void mma16816(float* c, const uint32_t* a, uint32_t b0,
                                         uint32_t b1) {
    asm volatile(
        "mma.sync.aligned.m16n8k16.row.col.f32.bf16.bf16.f32 "
        "{%0,%1,%2,%3}, {%4,%5,%6,%7}, {%8,%9}, {%0,%1,%2,%3};"
        : "+f"(c[0]), "+f"(c[1]), "+f"(c[2]), "+f"(c[3])
        : "r"(a[0]), "r"(a[1]), "r"(a[2]), "r"(a[3]), "r"(b0), "r"(b1));
}

#define PITCHB 80   // bytes per bf16 row (40 bf16); 8-row ldmatrix conflict-free

// ---------------------------------------------------------------------------
// Kernel 1: dist via mma.sync bf16 (unchanged from R5; 19.6us, L2-resident out)
// ---------------------------------------------------------------------------
__global__ __launch_bounds__(256) void dist_kernel(const float* __restrict__ x,
                                                   const float* __restrict__ y) {
    __shared__ __align__(16) char xs[256 * PITCHB];
    __shared__ __align__(16) char ys[256 * PITCHB];
    __shared__ float x2s[256];
    __shared__ float y2s[256];

    const int b = blockIdx.x, t = threadIdx.x;
    const int w = t >> 5, lane = t & 31;
    const float* xr = x + ((size_t)b * NN + t) * DIM;
    const float* yr = y + ((size_t)b * MM + t) * DIM;

    {
        float sx = 0.f, sy = 0.f;
#pragma unroll
        for (int q = 0; q < 8; q++) {
            float4 v = *(const float4*)(xr + q * 4);
            sx = fmaf(v.x, v.x, fmaf(v.y, v.y, fmaf(v.z, v.z, fmaf(v.w, v.w, sx))));
            uint2 wv;
            asm("cvt.rn.bf16x2.f32 %0, %1, %2;" : "=r"(wv.x) : "f"(v.y), "f"(v.x));
            asm("cvt.rn.bf16x2.f32 %0, %1, %2;" : "=r"(wv.y) : "f"(v.w), "f"(v.z));
            *(uint2*)(xs + t * PITCHB + q * 8) = wv;
            float4 u = *(const float4*)(yr + q * 4);
            sy = fmaf(u.x, u.x, fmaf(u.y, u.y, fmaf(u.z, u.z, fmaf(u.w, u.w, sy))));
            uint2 uv;
            asm("cvt.rn.bf16x2.f32 %0, %1, %2;" : "=r"(uv.x) : "f"(u.y), "f"(u.x));
            asm("cvt.rn.bf16x2.f32 %0, %1, %2;" : "=r"(uv.y) : "f"(u.w), "f"(u.z));
            *(uint2*)(ys + t * PITCHB + q * 8) = uv;
        }
        x2s[t] = sx;
        y2s[t] = sy;
    }
    __syncthreads();

    const uint32_t xsb = smem_u32(xs), ysb = smem_u32(ys);
    const int i0w = w * 32;

    uint32_t afr[2][2][4];
    {
        int rowA = i0w + (lane & 15);
        uint32_t base = xsb + rowA * PITCHB + ((lane >> 4) << 4);
#pragma unroll
        for (int rt = 0; rt < 2; rt++)
#pragma unroll
            for (int ks = 0; ks < 2; ks++)
                ldmx4(afr[rt][ks], base + rt * 16 * PITCHB + ks * 32);
    }

    float* gb = g_dist + (size_t)b * (NN * MM);
    const int rsub = lane >> 2;
    const int cpair = 2 * (lane & 3);

    for (int cg = 0; cg < 16; cg++) {
        const int c0 = cg * 16;
        uint32_t bbase = ysb + (c0 + (lane & 7) + ((lane & 16) >> 1)) * PITCHB +
                         ((lane >> 3) & 1) * 16;
        uint32_t b_k0[4], b_k1[4];
        ldmx4(b_k0, bbase);
        ldmx4(b_k1, bbase + 32);

#pragma unroll
        for (int rt = 0; rt < 2; rt++) {
            float C0[4] = {0.f, 0.f, 0.f, 0.f};
            float C1[4] = {0.f, 0.f, 0.f, 0.f};
            mma16816(C0, afr[rt][0], b_k0[0], b_k0[1]);
            mma16816(C0, afr[rt][1], b_k1[0], b_k1[1]);
            mma16816(C1, afr[rt][0], b_k0[2], b_k0[3]);
            mma16816(C1, afr[rt][1], b_k1[2], b_k1[3]);

            const int r_lo = i0w + rt * 16 + rsub;
            const float x2lo = x2s[r_lo], x2hi = x2s[r_lo + 8];
            const int rowtile = ((r_lo >> 4) * 16 + cg) * 256;
            const int rin_lo = (r_lo & 15) << 4, rin_hi = ((r_lo + 8) & 15) << 4;
#pragma unroll
            for (int nt = 0; nt < 2; nt++) {
                const float* C = nt ? C1 : C0;
                const int cc = c0 + nt * 8 + cpair;
                float2 yy = *(const float2*)(y2s + cc);
                float2 olo, ohi;
                olo.x = fmaxf(fmaf(-2.f, C[0], x2lo + yy.x), 0.f);
                olo.y = fmaxf(fmaf(-2.f, C[1], x2lo + yy.y), 0.f);
                ohi.x = fmaxf(fmaf(-2.f, C[2], x2hi + yy.x), 0.f);
                ohi.y = fmaxf(fmaf(-2.f, C[3], x2hi + yy.y), 0.f);
                const int cin = nt * 8 + cpair;
                *(float2*)(gb + rowtile + rin_lo + cin) = olo;
                *(float2*)(gb + rowtile + rin_hi + cin) = ohi;
            }
        }
    }
}

// ---------------------------------------------------------------------------
// Kernel 2: wavefront DP, shuffle-group version. 128 CTAs x 288 threads
// (9 warps), 2 batches per CTA (ILP-2). Lane l of warp w owns column
// j = 29w + l - 2; lanes 0-2 redundantly recompute the previous warp's last
// 3 columns so 4 diagonals run per __syncthreads, neighbors via shfl_up.
// Boundary (3 cols/warp) exchanged through smem at each group barrier.
// ---------------------------------------------------------------------------
#define RINGF 16384                 // floats per batch ring (4 slots x 4096)
#define NT 288
#define SMEM_DP ((2 * RINGF + 4 * 264) * 4)

__device__ __forceinline__ void issue_band(int T, const float* gb, uint32_t ringS, int t) {
    if (T > 30) return;
    int rt0 = T - 15 > 0 ? T - 15 : 0;
    int rt1 = T < 15 ? T : 15;
    int chunks = (rt1 - rt0 + 1) * 64;
    uint32_t slotbase = ringS + (uint32_t)((T & 3) * 4096 * 4);
    for (int n = t; n < chunks; n += NT) {
        int tile = n >> 6, wi = n & 63;
        int rt = rt0 + tile;
        const float* g = gb + ((rt * 16 + (T - rt)) * 256 + wi * 4);
        uint32_t s = slotbase + (uint32_t)(((rt & 15) * 256 + wi * 4) * 4);
        asm volatile("cp.async.cg.shared.global [%0], [%1], 16;" :: "r"(s), "l"(g));
    }
}

__global__ __launch_bounds__(NT) void dtw_kernel() {
    extern __shared__ float sm[];
    float* ring0 = sm;
    float* ring1 = sm + RINGF;
    float* bnd = sm + 2 * RINGF;   // 4 arrays of 264: b0v1, b0v0, b1v1, b1v0
    const int bb = blockIdx.x, t = threadIdx.x;
    const int w = t >> 5, l = t & 31;
    const int j = 29 * w + l - 2;          // owned column (may be <=0 or >256)
    const int c = j - 1;                   // dist column index
    const bool cval = ((unsigned)c < 256u);
    const int ct = cval ? (c >> 4) : 0, cin = cval ? (c & 15) : 0;

    const float* gb0 = g_dist + (size_t)(2 * bb) * (NN * MM);
    const float* gb1 = g_dist + (size_t)(2 * bb + 1) * (NN * MM);
    uint32_t rs0 = smem_u32(ring0), rs1 = smem_u32(ring1);

    float v1_0 = BIGF, v0_0 = (j == 0) ? 0.f : BIGF;
    float v1_1 = BIGF, v0_1 = v0_0;

    // seed boundary for group 0
    if (w < 8 && l >= 29) {
        bnd[j] = v1_0; bnd[264 + j] = v0_0;
        bnd[528 + j] = v1_1; bnd[792 + j] = v0_1;
    }

    issue_band(0, gb0, rs0, t);
    issue_band(0, gb1, rs1, t);
    asm volatile("cp.async.commit_group;");

    for (int g = 0; g < 128; ++g) {
        if ((g & 3) == 0) {
            int U = g >> 2;
            issue_band(U + 1, gb0, rs0, t);
            issue_band(U + 1, gb1, rs1, t);
            asm volatile("cp.async.commit_group;");
            asm volatile("cp.async.wait_group 1;");
        }
        __syncthreads();   // band visible + boundary exchange

        if (l < 3 && w > 0) {   // refresh redundant lanes
            v1_0 = bnd[j]; v0_0 = bnd[264 + j];
            v1_1 = bnd[528 + j]; v0_1 = bnd[792 + j];
        }

        const int p0 = 2 + 4 * g;
        // prefetch the 4 dist values per batch (off critical path)
        float dq0[4], dq1[4];
#pragma unroll
        for (int s = 0; s < 4; s++) {
            int r = p0 + s - j - 1;
            bool val = cval && ((unsigned)r < 256u);
            int rr = val ? r : 0;
            int off = ((((rr >> 4) + ct) & 3) << 12) + (((rr >> 4) & 15) << 8) +
                      ((rr & 15) << 4) + cin;
            dq0[s] = val ? ring0[off] : 0.f;
            dq1[s] = val ? ring1[off] : 0.f;
        }

        float dgp0 = __shfl_up_sync(0xffffffffu, v0_0, 1);
        float dgp1 = __shfl_up_sync(0xffffffffu, v0_1, 1);

#pragma unroll
        for (int s = 0; s < 4; s++) {
            const int p = p0 + s;
            const int i = p - j;
            float lf0 = __shfl_up_sync(0xffffffffu, v1_0, 1);
            float lf1 = __shfl_up_sync(0xffffffffu, v1_1, 1);
            const bool val = cval && ((unsigned)(i - 1) < 256u);

            float up0 = v1_0, dg0 = dgp0;
            float up1 = v1_1, dg1 = dgp1;
            float mn0 = fminf(fminf(up0, lf0), dg0);
            float mx0 = fmaxf(fmaxf(up0, lf0), dg0);
            float md0 = fmaxf(fminf(up0, lf0), fminf(fmaxf(up0, lf0), dg0));
            float mn1 = fminf(fminf(up1, lf1), dg1);
            float mx1 = fmaxf(fmaxf(up1, lf1), dg1);
            float md1 = fmaxf(fminf(up1, lf1), fminf(fmaxf(up1, lf1), dg1));
            float s0 = 1.0f + __expf(mn0 - md0) + __expf(mn0 - mx0);
            float s1 = 1.0f + __expf(mn1 - md1) + __expf(mn1 - mx1);
            float nv0 = dq0[s] + mn0 - __logf(s0);
            float nv1 = dq1[s] + mn1 - __logf(s1);
            nv0 = val ? nv0 : BIGF;
            nv1 = val ? nv1 : BIGF;

            if (p == NN + MM && j == MM) {
                g_partial[2 * bb] = nv0;
                g_partial[2 * bb + 1] = nv1;
            }
            dgp0 = lf0; dgp1 = lf1;
            v0_0 = v1_0; v1_0 = nv0;
            v0_1 = v1_1; v1_1 = nv1;
        }

        if (w < 8 && l >= 29) {   // publish boundary for next warp's lanes 0-2
            bnd[j] = v1_0; bnd[264 + j] = v0_0;
            bnd[528 + j] = v1_1; bnd[792 + j] = v0_1;
        }
    }
}

// ---------------------------------------------------------------------------
// Kernel 3: mean over batches -> scalar output.
// ---------------------------------------------------------------------------
__global__ __launch_bounds__(256) void reduce_kernel(float* __restrict__ out) {
    __shared__ float sb[256];
    int t = threadIdx.x;
    sb[t] = g_partial[t];
    __syncthreads();
    for (int s = 128; s > 0; s >>= 1) {
        if (t < s) sb[t] += sb[t + s];
        __syncthreads();
    }
    if (t == 0) out[0] = sb[0] * (1.0f / BATCH);
}

extern "C" void kernel_launch(void* const* d_in, const int* in_sizes, int n_in,
                              void* d_out, int out_size) {
    (void)in_sizes; (void)n_in; (void)out_size;
    const float* x = (const float*)d_in[0];
    const float* y = (const float*)d_in[1];
    float* out = (float*)d_out;

    cudaFuncSetAttribute(dtw_kernel, cudaFuncAttributeMaxDynamicSharedMemorySize,
                         SMEM_DP);

    dist_kernel<<<BATCH, 256>>>(x, y);
    dtw_kernel<<<BATCH / 2, NT, SMEM_DP>>>();
    reduce_kernel<<<1, 256>>>(out);
}